// round 3
// baseline (speedup 1.0000x reference)
#include <cuda_runtime.h>
#include <cuda_bf16.h>

#define BATCH   16384
#define EMBED   64
#define N_EDGES 524288
#define FULL    0xffffffffu

// Scratch (device globals — no allocation allowed).
// Both arrays are FULLY overwritten every launch -> no zeroing needed.
__device__ int   g_off[BATCH + 1];       // CSR row offsets into edge list
__device__ float g_mean[BATCH * EMBED];  // per-row neighbor mean

// ---------------------------------------------------------------------------
// Kernel 1: boundary scatter. seg_ids is sorted; thread e writes
// g_off[s] = e for every segment s that starts at edge e. Every entry of
// g_off[0..BATCH] is written exactly once (empty segments + head + tail
// covered), so the kernel is idempotent across graph replays.
// ---------------------------------------------------------------------------
__global__ void offsets_kernel(const int* __restrict__ seg_ids) {
    const int e = blockIdx.x * blockDim.x + threadIdx.x;
    if (e >= N_EDGES) return;
    const int s_cur  = seg_ids[e];
    const int s_prev = (e == 0) ? -1 : seg_ids[e - 1];
    for (int s = s_prev + 1; s <= s_cur; ++s) g_off[s] = e;
    if (e == N_EDGES - 1)
        for (int s = s_cur + 1; s <= BATCH; ++s) g_off[s] = N_EDGES;
}

// ---------------------------------------------------------------------------
// Kernel 2: warp-per-row neighbor mean. No atomics, no branches on segment
// changes: warp owns row b, gathers its edge range with 8 independent 256B
// row loads in flight, writes the mean once with a plain float2 store.
// Lane covers 2 of the 64 dims (float2) -> one coalesced 256B row per load.
// ---------------------------------------------------------------------------
__global__ void agg_kernel(const int*   __restrict__ neigh_ids,
                           const float* __restrict__ features) {
    const int b    = (blockIdx.x * blockDim.x + threadIdx.x) >> 5;
    const int lane = threadIdx.x & 31;
    if (b >= BATCH) return;

    const int lo  = g_off[b];
    const int hi  = g_off[b + 1];
    const int cnt = hi - lo;

    const float2* __restrict__ feats2 = (const float2*)features;
    float2 acc = make_float2(0.0f, 0.0f);

    for (int c = lo; c < hi; c += 32) {
        const int m = min(32, hi - c);
        const int myid = (lane < m) ? neigh_ids[c + lane] : 0;  // coalesced

        for (int u0 = 0; u0 < m; u0 += 8) {
            const int nb = m - u0;            // >=1; use min(nb,8) valid
            int    n[8];
            float2 v[8];
            #pragma unroll
            for (int u = 0; u < 8; ++u) n[u] = __shfl_sync(FULL, myid, u0 + u);
            #pragma unroll
            for (int u = 0; u < 8; ++u)       // up to 8 loads in flight
                if (u < nb) v[u] = feats2[(size_t)n[u] * 32 + lane];
            #pragma unroll
            for (int u = 0; u < 8; ++u)
                if (u < nb) { acc.x += v[u].x; acc.y += v[u].y; }
        }
    }

    const float inv = 1.0f / fmaxf((float)cnt, 1.0f);
    ((float2*)g_mean)[(size_t)b * 32 + lane] =
        make_float2(acc.x * inv, acc.y * inv);
}

// ---------------------------------------------------------------------------
// Kernel 3: self gather + [self | neigh_mean] @ w1^T + b1, relu.
// Register-tiled weights: 256 threads = 4 k-groups (warp-uniform) x 64 output
// dims; each thread holds 32 w1 values in registers. comb reads are float4
// broadcast LDS; partials reduced through stride-5-padded smem.
// ---------------------------------------------------------------------------
__global__ void mlp_kernel(const int*   __restrict__ nodes,
                           const float* __restrict__ features,
                           const float* __restrict__ w1,
                           const float* __restrict__ b1,
                           float*       __restrict__ out) {
    __shared__ float w1s[64 * 129];       // staged w1, row stride 129 (pad)
    __shared__ float b1s[64];
    __shared__ float comb[4][128];        // 4 rows of concat(self, neigh_mean)
    __shared__ float part[4][64 * 5];     // partials, stride-5 pad over g

    for (int idx = threadIdx.x; idx < 64 * 128; idx += blockDim.x) {
        const int j = idx >> 7;
        const int k = idx & 127;
        w1s[j * 129 + k] = w1[idx];       // w1 row-major (64,128)
    }
    if (threadIdx.x < 64) b1s[threadIdx.x] = b1[threadIdx.x];
    __syncthreads();

    const int g = threadIdx.x >> 6;       // k-group 0..3 (warp-uniform)
    const int j = threadIdx.x & 63;       // output dim

    // per-thread weight registers: w1[j][g*32 .. g*32+31] (conflict-free fill)
    float w[32];
    #pragma unroll
    for (int kk = 0; kk < 32; ++kk) w[kk] = w1s[j * 129 + g * 32 + kk];

    const int r = threadIdx.x >> 6;       // row used during fill/writeback
    for (int base = blockIdx.x * 4; base < BATCH; base += gridDim.x * 4) {
        {
            const int b = base + r;
            const int node = nodes[b];
            comb[r][j]      = features[(size_t)node * EMBED + j];
            comb[r][64 + j] = g_mean[b * EMBED + j];
        }
        __syncthreads();

        #pragma unroll
        for (int rr = 0; rr < 4; ++rr) {
            const float4* c4 = (const float4*)&comb[rr][g * 32];
            float p = 0.0f;
            #pragma unroll
            for (int q = 0; q < 8; ++q) {     // float4 broadcast LDS
                const float4 c = c4[q];
                p = fmaf(c.x, w[q * 4 + 0], p);
                p = fmaf(c.y, w[q * 4 + 1], p);
                p = fmaf(c.z, w[q * 4 + 2], p);
                p = fmaf(c.w, w[q * 4 + 3], p);
            }
            part[rr][j * 5 + g] = p;          // conflict-free (5 coprime 32)
        }
        __syncthreads();

        {
            const int b = base + r;
            const float s = part[r][j * 5 + 0] + part[r][j * 5 + 1] +
                            part[r][j * 5 + 2] + part[r][j * 5 + 3] + b1s[j];
            out[(size_t)b * EMBED + j] = fmaxf(s, 0.0f);
        }
        __syncthreads();
    }
}

// ---------------------------------------------------------------------------
// Launch
// inputs: nodes(i32,16384) neigh_ids(i32,524288) seg_ids(i32,524288)
//         features(f32,64M) w1(f32,8192) b1(f32,64)   output: f32 (16384,64)
// ---------------------------------------------------------------------------
extern "C" void kernel_launch(void* const* d_in, const int* in_sizes, int n_in,
                              void* d_out, int out_size) {
    const int*   nodes     = (const int*)  d_in[0];
    const int*   neigh_ids = (const int*)  d_in[1];
    const int*   seg_ids   = (const int*)  d_in[2];
    const float* features  = (const float*)d_in[3];
    const float* w1        = (const float*)d_in[4];
    const float* b1        = (const float*)d_in[5];
    float*       out       = (float*)d_out;

    offsets_kernel<<<N_EDGES / 256, 256>>>(seg_ids);

    // 16384 rows, warp per row, 8 warps per block
    agg_kernel<<<BATCH / 8, 256>>>(neigh_ids, features);

    mlp_kernel<<<512, 256>>>(nodes, features, w1, b1, out);
}

// round 4
// speedup vs baseline: 1.2719x; 1.2719x over previous
#include <cuda_runtime.h>
#include <cuda_bf16.h>

#define BATCH   16384
#define EMBED   64
#define N_EDGES 524288
#define FULL    0xffffffffu

// Scratch (device globals — no allocation allowed)
__device__ float g_acc[BATCH * EMBED];   // 4 MB segment sums
__device__ float g_cnt[BATCH];           // segment counts

// ---------------------------------------------------------------------------
// Kernel 1: zero accumulators (float4, single stride loop)
// total float4s: 262144 (g_acc) + 4096 (g_cnt)
// ---------------------------------------------------------------------------
__global__ void zero_kernel() {
    const int i = blockIdx.x * blockDim.x + threadIdx.x;
    const float4 z = make_float4(0.f, 0.f, 0.f, 0.f);
    if (i < 262144)       ((float4*)g_acc)[i] = z;
    else if (i < 266240)  ((float4*)g_cnt)[i - 262144] = z;
}

// ---------------------------------------------------------------------------
// Kernel 2: edge aggregation. One warp owns 32 consecutive edges (static,
// compile-time partitioning). ids loaded lane-parallel (coalesced) and
// broadcast via shfl. Feature rows fetched in batches of 16 independent
// 256B loads -> deep MLP. seg_ids sorted: register run-compression, atomic
// flush only on segment change (~2 flushes/warp avg).
// ---------------------------------------------------------------------------
__global__ void agg_kernel(const int*   __restrict__ neigh_ids,
                           const int*   __restrict__ seg_ids,
                           const float* __restrict__ features) {
    const int warp = (blockIdx.x * blockDim.x + threadIdx.x) >> 5;
    const int lane = threadIdx.x & 31;
    const int e0 = warp * 32;
    if (e0 >= N_EDGES) return;

    // coalesced: lane l owns ids of edge e0+l
    const int my_seg = seg_ids[e0 + lane];
    const int my_nid = neigh_ids[e0 + lane];

    const float2* __restrict__ feats2 = (const float2*)features;

    float2 acc = make_float2(0.0f, 0.0f);
    int cur = __shfl_sync(FULL, my_seg, 0);
    int runlen = 0;

    #pragma unroll
    for (int c = 0; c < 32; c += 16) {
        int    n[16], s[16];
        float2 v[16];
        #pragma unroll
        for (int u = 0; u < 16; ++u) n[u] = __shfl_sync(FULL, my_nid, c + u);
        // 16 independent 256B row loads in flight
        #pragma unroll
        for (int u = 0; u < 16; ++u) v[u] = feats2[(size_t)n[u] * 32 + lane];
        #pragma unroll
        for (int u = 0; u < 16; ++u) s[u] = __shfl_sync(FULL, my_seg, c + u);
        #pragma unroll
        for (int u = 0; u < 16; ++u) {
            if (s[u] != cur) {            // warp-uniform (s is broadcast)
                atomicAdd(&g_acc[cur * EMBED + 2 * lane],     acc.x);
                atomicAdd(&g_acc[cur * EMBED + 2 * lane + 1], acc.y);
                if (lane == 0) atomicAdd(&g_cnt[cur], (float)runlen);
                acc = make_float2(0.0f, 0.0f);
                cur = s[u];
                runlen = 0;
            }
            acc.x += v[u].x;
            acc.y += v[u].y;
            ++runlen;
        }
    }
    atomicAdd(&g_acc[cur * EMBED + 2 * lane],     acc.x);
    atomicAdd(&g_acc[cur * EMBED + 2 * lane + 1], acc.y);
    if (lane == 0) atomicAdd(&g_cnt[cur], (float)runlen);
}

// ---------------------------------------------------------------------------
// Kernel 3: self gather + mean + [self|neigh] @ w1^T + b1, relu.
// Register-tiled weights: 256 threads = 4 k-groups (warp-uniform) x 64 output
// dims; each thread holds 32 w1 values in registers (conflict-free fill from
// stride-129-padded smem). comb reads are float4 broadcast LDS; partials
// reduced through stride-5-padded smem.
// ---------------------------------------------------------------------------
__global__ void mlp_kernel(const int*   __restrict__ nodes,
                           const float* __restrict__ features,
                           const float* __restrict__ w1,
                           const float* __restrict__ b1,
                           float*       __restrict__ out) {
    __shared__ float w1s[64 * 129];
    __shared__ float b1s[64];
    __shared__ float comb[4][128];
    __shared__ float part[4][64 * 5];

    for (int idx = threadIdx.x; idx < 64 * 128; idx += blockDim.x) {
        const int j = idx >> 7;
        const int k = idx & 127;
        w1s[j * 129 + k] = w1[idx];       // w1 row-major (64,128)
    }
    if (threadIdx.x < 64) b1s[threadIdx.x] = b1[threadIdx.x];
    __syncthreads();

    const int g = threadIdx.x >> 6;       // k-group 0..3 (warp-uniform)
    const int j = threadIdx.x & 63;       // output dim

    float w[32];
    #pragma unroll
    for (int kk = 0; kk < 32; ++kk) w[kk] = w1s[j * 129 + g * 32 + kk];

    const int r = threadIdx.x >> 6;
    for (int base = blockIdx.x * 4; base < BATCH; base += gridDim.x * 4) {
        {
            const int b = base + r;
            const int node = nodes[b];
            comb[r][j]      = features[(size_t)node * EMBED + j];
            const float inv = 1.0f / fmaxf(g_cnt[b], 1.0f);
            comb[r][64 + j] = g_acc[b * EMBED + j] * inv;
        }
        __syncthreads();

        #pragma unroll
        for (int rr = 0; rr < 4; ++rr) {
            const float4* c4 = (const float4*)&comb[rr][g * 32];
            float p = 0.0f;
            #pragma unroll
            for (int q = 0; q < 8; ++q) {     // float4 broadcast LDS
                const float4 c = c4[q];
                p = fmaf(c.x, w[q * 4 + 0], p);
                p = fmaf(c.y, w[q * 4 + 1], p);
                p = fmaf(c.z, w[q * 4 + 2], p);
                p = fmaf(c.w, w[q * 4 + 3], p);
            }
            part[rr][j * 5 + g] = p;          // conflict-free (5 coprime 32)
        }
        __syncthreads();

        {
            const int b = base + r;
            const float s = part[r][j * 5 + 0] + part[r][j * 5 + 1] +
                            part[r][j * 5 + 2] + part[r][j * 5 + 3] + b1s[j];
            out[(size_t)b * EMBED + j] = fmaxf(s, 0.0f);
        }
        __syncthreads();
    }
}

// ---------------------------------------------------------------------------
// Launch
// inputs: nodes(i32,16384) neigh_ids(i32,524288) seg_ids(i32,524288)
//         features(f32,64M) w1(f32,8192) b1(f32,64)   output: f32 (16384,64)
// ---------------------------------------------------------------------------
extern "C" void kernel_launch(void* const* d_in, const int* in_sizes, int n_in,
                              void* d_out, int out_size) {
    const int*   nodes     = (const int*)  d_in[0];
    const int*   neigh_ids = (const int*)  d_in[1];
    const int*   seg_ids   = (const int*)  d_in[2];
    const float* features  = (const float*)d_in[3];
    const float* w1        = (const float*)d_in[4];
    const float* b1        = (const float*)d_in[5];
    float*       out       = (float*)d_out;

    zero_kernel<<<(266240 + 255) / 256, 256>>>();

    const int n_warps = N_EDGES / 32;             // 16384 warps
    agg_kernel<<<n_warps / 8, 256>>>(neigh_ids, seg_ids, features);

    mlp_kernel<<<1024, 256>>>(nodes, features, w1, b1, out);
}

// round 5
// speedup vs baseline: 1.3266x; 1.0430x over previous
#include <cuda_runtime.h>
#include <cuda_bf16.h>

#define BATCH   16384
#define EMBED   64
#define N_EDGES 524288
#define FULL    0xffffffffu

// Scratch (device globals — no allocation allowed)
__device__ float g_acc[BATCH * EMBED];   // 4 MB segment sums
__device__ float g_cnt[BATCH];           // segment counts

// ---------------------------------------------------------------------------
// Kernel 1: zero accumulators (float4)
// ---------------------------------------------------------------------------
__global__ void zero_kernel() {
    const int i = blockIdx.x * blockDim.x + threadIdx.x;
    const float4 z = make_float4(0.f, 0.f, 0.f, 0.f);
    if (i < 262144)       ((float4*)g_acc)[i] = z;
    else if (i < 266240)  ((float4*)g_cnt)[i - 262144] = z;
}

// ---------------------------------------------------------------------------
// Kernel 2 (R2 version — proven best): warp owns 32 consecutive edges,
// ids coalesced + shfl-broadcast, 8 independent 256B row loads in flight,
// register run-compression on the sorted seg_ids, atomic flush on change.
// ---------------------------------------------------------------------------
__global__ void agg_kernel(const int*   __restrict__ neigh_ids,
                           const int*   __restrict__ seg_ids,
                           const float* __restrict__ features) {
    const int warp = (blockIdx.x * blockDim.x + threadIdx.x) >> 5;
    const int lane = threadIdx.x & 31;
    const int e0 = warp * 32;
    if (e0 >= N_EDGES) return;

    const int my_seg = seg_ids[e0 + lane];
    const int my_nid = neigh_ids[e0 + lane];

    const float2* __restrict__ feats2 = (const float2*)features;

    float2 acc = make_float2(0.0f, 0.0f);
    int cur = __shfl_sync(FULL, my_seg, 0);
    int runlen = 0;

    #pragma unroll
    for (int c = 0; c < 32; c += 8) {
        int    n[8], s[8];
        float2 v[8];
        #pragma unroll
        for (int u = 0; u < 8; ++u) n[u] = __shfl_sync(FULL, my_nid, c + u);
        #pragma unroll
        for (int u = 0; u < 8; ++u) v[u] = feats2[(size_t)n[u] * 32 + lane];
        #pragma unroll
        for (int u = 0; u < 8; ++u) s[u] = __shfl_sync(FULL, my_seg, c + u);
        #pragma unroll
        for (int u = 0; u < 8; ++u) {
            if (s[u] != cur) {            // warp-uniform (s is broadcast)
                atomicAdd(&g_acc[cur * EMBED + 2 * lane],     acc.x);
                atomicAdd(&g_acc[cur * EMBED + 2 * lane + 1], acc.y);
                if (lane == 0) atomicAdd(&g_cnt[cur], (float)runlen);
                acc = make_float2(0.0f, 0.0f);
                cur = s[u];
                runlen = 0;
            }
            acc.x += v[u].x;
            acc.y += v[u].y;
            ++runlen;
        }
    }
    atomicAdd(&g_acc[cur * EMBED + 2 * lane],     acc.x);
    atomicAdd(&g_acc[cur * EMBED + 2 * lane + 1], acc.y);
    if (lane == 0) atomicAdd(&g_cnt[cur], (float)runlen);
}

// ---------------------------------------------------------------------------
// Kernel 3: self gather + mean + [self|neigh] @ w1^T + b1, relu.
// Packed f32x2 FMA (fma.rn.f32x2): k-pairs packed into b64 operands.
// comb read as ulonglong2 (LDS.128 = two packed pairs, zero movs), weights
// pre-packed into 16 b64 registers per thread. Halves fma-pipe occupancy
// vs scalar FFMA (rt_SMSP=2 either way, 2 floats per instr).
// ---------------------------------------------------------------------------
__global__ void mlp_kernel(const int*   __restrict__ nodes,
                           const float* __restrict__ features,
                           const float* __restrict__ w1,
                           const float* __restrict__ b1,
                           float*       __restrict__ out) {
    __shared__ float w1s[64 * 129];                 // padded stage of w1
    __shared__ float b1s[64];
    __shared__ __align__(16) float comb[4][128];    // 4 rows of concat
    __shared__ float part[4][64 * 5];               // stride-5 padded partials

    for (int idx = threadIdx.x; idx < 64 * 128; idx += blockDim.x) {
        const int j = idx >> 7;
        const int k = idx & 127;
        w1s[j * 129 + k] = w1[idx];                 // w1 row-major (64,128)
    }
    if (threadIdx.x < 64) b1s[threadIdx.x] = b1[threadIdx.x];
    __syncthreads();

    const int g = threadIdx.x >> 6;                 // k-group 0..3
    const int j = threadIdx.x & 63;                 // output dim

    // packed weight pairs: w2[kk] = {w1[j][g*32+2kk], w1[j][g*32+2kk+1]}
    unsigned long long w2[16];
    #pragma unroll
    for (int kk = 0; kk < 16; ++kk) {
        const float lo = w1s[j * 129 + g * 32 + 2 * kk];
        const float hi = w1s[j * 129 + g * 32 + 2 * kk + 1];
        asm("mov.b64 %0, {%1, %2};" : "=l"(w2[kk]) : "f"(lo), "f"(hi));
    }

    const int r = threadIdx.x >> 6;                 // row for fill/writeback
    for (int base = blockIdx.x * 4; base < BATCH; base += gridDim.x * 4) {
        {
            const int b = base + r;
            const int node = nodes[b];
            comb[r][j]      = features[(size_t)node * EMBED + j];
            const float inv = 1.0f / fmaxf(g_cnt[b], 1.0f);
            comb[r][64 + j] = g_acc[b * EMBED + j] * inv;
        }
        __syncthreads();

        #pragma unroll
        for (int rr = 0; rr < 4; ++rr) {
            const ulonglong2* c2 = (const ulonglong2*)&comb[rr][g * 32];
            unsigned long long acc = 0ull;          // packed {0.0f, 0.0f}
            #pragma unroll
            for (int q = 0; q < 8; ++q) {           // 8 x LDS.128 broadcast
                const ulonglong2 c = c2[q];
                asm("fma.rn.f32x2 %0, %1, %2, %0;"
                    : "+l"(acc) : "l"(c.x), "l"(w2[2 * q]));
                asm("fma.rn.f32x2 %0, %1, %2, %0;"
                    : "+l"(acc) : "l"(c.y), "l"(w2[2 * q + 1]));
            }
            float lo, hi;
            asm("mov.b64 {%0, %1}, %2;" : "=f"(lo), "=f"(hi) : "l"(acc));
            part[rr][j * 5 + g] = lo + hi;          // conflict-free (5⊥32)
        }
        __syncthreads();

        {
            const int b = base + r;
            const float s = part[r][j * 5 + 0] + part[r][j * 5 + 1] +
                            part[r][j * 5 + 2] + part[r][j * 5 + 3] + b1s[j];
            out[(size_t)b * EMBED + j] = fmaxf(s, 0.0f);
        }
        __syncthreads();
    }
}

// ---------------------------------------------------------------------------
// Launch
// inputs: nodes(i32,16384) neigh_ids(i32,524288) seg_ids(i32,524288)
//         features(f32,64M) w1(f32,8192) b1(f32,64)   output: f32 (16384,64)
// ---------------------------------------------------------------------------
extern "C" void kernel_launch(void* const* d_in, const int* in_sizes, int n_in,
                              void* d_out, int out_size) {
    const int*   nodes     = (const int*)  d_in[0];
    const int*   neigh_ids = (const int*)  d_in[1];
    const int*   seg_ids   = (const int*)  d_in[2];
    const float* features  = (const float*)d_in[3];
    const float* w1        = (const float*)d_in[4];
    const float* b1        = (const float*)d_in[5];
    float*       out       = (float*)d_out;

    zero_kernel<<<(266240 + 255) / 256, 256>>>();

    const int n_warps = N_EDGES / 32;             // 16384 warps
    agg_kernel<<<n_warps / 8, 256>>>(neigh_ids, seg_ids, features);

    // 148 SMs x 3 resident blocks — few prologues, many loop iterations
    mlp_kernel<<<444, 256>>>(nodes, features, w1, b1, out);
}